// round 4
// baseline (speedup 1.0000x reference)
#include <cuda_runtime.h>
#include <cstdint>

// Problem constants (static per reference)
#define BB    8
#define NNODE 384
#define FF    64
#define TT    192
#define NSRC  383         // T + TAU - 1
#define NROWS (5*BB*TT)   // S*B*192 = 7680 argmax rows

typedef unsigned long long ull;

// ---------------- device scratch (no allocs allowed) ----------------
__device__ float g_P[BB*NNODE*FF];        // nodes @ w1_top + b1  (sink half)
__device__ float g_Q[BB*NNODE*FF];        // nodes @ w1_bot       (src half)
__device__ float g_logits[BB*TT*NSRC];    // per-edge logits, dense (b, i, c)

// ---------------- helpers ----------------
__device__ __forceinline__ void fma2(ull &d, ull a, ull b) {
    // paired fp32 FMA (FFMA2): d.lo += a.lo*b.lo; d.hi += a.hi*b.hi
    asm("fma.rn.f32x2 %0, %1, %2, %0;" : "+l"(d) : "l"(a), "l"(b));
}
__device__ __forceinline__ float2 unpack2(ull v) {
    float2 r;
    asm("mov.b64 {%0, %1}, %2;" : "=f"(r.x), "=f"(r.y) : "l"(v));
    return r;
}

// swizzled address (in floats) of element (row e, k) inside H1s:
// 16B units, unit u = k>>2, physical unit = u ^ (e & 15).
// LDS/STS.128 are serviced in lane-octets; within any octet the low 3 bits of
// (u ^ e) are distinct -> conflict-free.
__device__ __forceinline__ int h1_addr(int e, int k) {
    return e*64 + ((((k >> 2) ^ (e & 15)) << 2) | (k & 3));
}
__device__ __forceinline__ int h1_unit(int e, int u) {
    return e*64 + ((u ^ (e & 15)) << 2);
}

// ---------------- K1: factor layer 1 per-node ----------------
__global__ void k_precompute(const float* __restrict__ nodes,
                             const float* __restrict__ w1,
                             const float* __restrict__ b1)
{
    __shared__ float w1s[128*64];
    __shared__ float nds[4][64];
    int tid = threadIdx.x;
    for (int idx = tid; idx < 128*64; idx += 256) w1s[idx] = w1[idx];
    __syncthreads();
    int f = tid & 63, slot = tid >> 6;
    int row0 = blockIdx.x * 32;                 // 96 blocks * 32 rows = 3072
    for (int r = 0; r < 32; r += 4) {
        int row = row0 + r + slot;
        nds[slot][f] = nodes[row*64 + f];
        __syncthreads();
        float accp = b1[f], accq = 0.f;
        #pragma unroll
        for (int k = 0; k < 64; k++) {
            float nv = nds[slot][k];
            accp = fmaf(nv, w1s[k*64 + f],       accp);
            accq = fmaf(nv, w1s[(64+k)*64 + f],  accq);
        }
        g_P[row*64 + f] = accp;
        g_Q[row*64 + f] = accq;
        __syncthreads();
    }
}

// ---------------- K2: fused edge MLP -> logits (shuffle-free) ----------------
// Block = 128 threads = 4 warps, 128 edges. Warp w owns edges [32w, 32w+32):
// phase1 thread-per-edge LN1 -> smem H1 (swizzled); GEMM 8-edge x 2-j f32x2
// register blocking, x written back into own (dead) H1 rows; epilogue
// thread-per-edge LN2 + w3 dot. Only warp-level syncs after one staging sync.
#define SMEM_FLOATS (8192 + 4096 + 448)
__global__ void __launch_bounds__(128, 4) k_edges(
    const float* __restrict__ w2,  const float* __restrict__ b2,
    const float* __restrict__ g2,  const float* __restrict__ be2,
    const float* __restrict__ w3,  const float* __restrict__ b3,
    const float* __restrict__ g1,  const float* __restrict__ be1)
{
    extern __shared__ float smem[];
    float* H1s   = smem;             // [128][64] swizzled
    float* W2f   = smem + 8192;      // [64 j][16 u][4] : w2[4u..4u+3][j]
    float* sp_p  = smem + 12288;     // 64
    float* sp_b2 = sp_p  + 64;
    float* sp_g1 = sp_b2 + 64;
    float* sp_be1= sp_g1 + 64;
    float* sp_g2 = sp_be1+ 64;
    float* sp_be2= sp_g2 + 64;
    float* sp_w3 = sp_be2+ 64;

    int i = blockIdx.y, b = blockIdx.z;
    int sink = 192 + i;
    int L = sink;                       // valid sources: c in [0, sink)
    int c_base = blockIdx.x * 128;
    if (c_base >= L) return;            // uniform early exit

    int tid  = threadIdx.x;
    int lane = tid & 31;
    int w    = tid >> 5;

    // ---- staging: w2 (j-major, 4-k units) + small params ----
    for (int idx = tid; idx < 4096; idx += 128) {
        int t = idx & 3, u = (idx >> 2) & 15, j = idx >> 6;
        W2f[idx] = w2[(4*u + t)*64 + j];
    }
    if (tid < 64) {
        sp_p[tid]  = g_P[(b*NNODE + sink)*64 + tid];
        sp_b2[tid] = b2[tid];
        sp_g1[tid] = g1[tid];
        sp_be1[tid]= be1[tid];
        sp_g2[tid] = g2[tid];
        sp_be2[tid]= be2[tid];
        sp_w3[tid] = w3[tid];
    }
    __syncthreads();

    // ---- phase 1: thread-per-edge LN1, all 64 dims in registers ----
    {
        int e = tid;                          // 0..127
        int c = c_base + e;                   // < 384: always safe to read
        const float4* qrow = (const float4*)&g_Q[((b*NNODE) + c)*64];
        float4 x[16];
        float s = 0.f;
        #pragma unroll
        for (int u = 0; u < 16; u++) {
            float4 q = __ldg(&qrow[u]);
            float4 p = *(const float4*)&sp_p[u*4];
            x[u].x = fmaxf(p.x + q.x, 0.f);
            x[u].y = fmaxf(p.y + q.y, 0.f);
            x[u].z = fmaxf(p.z + q.z, 0.f);
            x[u].w = fmaxf(p.w + q.w, 0.f);
            s += x[u].x + x[u].y + x[u].z + x[u].w;
        }
        float mu = s * (1.f/64.f);
        float vs = 0.f;
        #pragma unroll
        for (int u = 0; u < 16; u++) {
            float d0 = x[u].x - mu, d1 = x[u].y - mu;
            float d2 = x[u].z - mu, d3 = x[u].w - mu;
            vs += d0*d0 + d1*d1 + d2*d2 + d3*d3;
        }
        float rstd = 1.f / sqrtf(vs * (1.f/64.f) + 1e-5f);
        #pragma unroll
        for (int u = 0; u < 16; u++) {
            float4 gv = *(const float4*)&sp_g1[u*4];
            float4 bv = *(const float4*)&sp_be1[u*4];
            float4 h;
            h.x = fmaf((x[u].x - mu)*rstd, gv.x, bv.x);
            h.y = fmaf((x[u].y - mu)*rstd, gv.y, bv.y);
            h.z = fmaf((x[u].z - mu)*rstd, gv.z, bv.z);
            h.w = fmaf((x[u].w - mu)*rstd, gv.w, bv.w);
            *(float4*)&H1s[h1_unit(e, u)] = h;
        }
    }
    __syncwarp();

    // ---- phase 2: f32x2 GEMM, warp owns 32 edges in 4 passes of 8 ----
    {
        const ulonglong2* W2q = (const ulonglong2*)W2f;   // [j*16 + u]
        float b2a = sp_b2[lane], b2b = sp_b2[lane + 32];

        #pragma unroll 1
        for (int pass = 0; pass < 4; pass++) {
            int e0 = w*32 + pass*8;
            ull accA[8], accB[8];
            #pragma unroll
            for (int ee = 0; ee < 8; ee++) { accA[ee] = 0ull; accB[ee] = 0ull; }

            #pragma unroll
            for (int u = 0; u < 16; u++) {
                ulonglong2 wv0 = W2q[lane*16 + u];          // j = lane
                ulonglong2 wv1 = W2q[(lane + 32)*16 + u];   // j = lane+32
                #pragma unroll
                for (int ee = 0; ee < 8; ee++) {
                    const ulonglong2 hv =
                        *(const ulonglong2*)&H1s[h1_unit(e0 + ee, u)];  // bcast
                    fma2(accA[ee], hv.x, wv0.x);
                    fma2(accA[ee], hv.y, wv0.y);
                    fma2(accB[ee], hv.x, wv1.x);
                    fma2(accB[ee], hv.y, wv1.y);
                }
            }
            __syncwarp();   // all lanes done reading these 8 rows
            #pragma unroll
            for (int ee = 0; ee < 8; ee++) {
                int e = e0 + ee;
                float2 ta = unpack2(accA[ee]);
                float2 tb = unpack2(accB[ee]);
                float xa = fmaxf(ta.x + ta.y + b2a, 0.f);   // relu(h1@w2 + b2)
                float xb = fmaxf(tb.x + tb.y + b2b, 0.f);
                H1s[h1_addr(e, lane)]      = xa;            // overwrite own row
                H1s[h1_addr(e, lane + 32)] = xb;
            }
        }
    }
    __syncwarp();

    // ---- phase 3: thread-per-edge LN2 + logit ----
    {
        int e = w*32 + lane;                 // row this warp wrote
        float4 xx[16];
        float s = 0.f;
        #pragma unroll
        for (int u = 0; u < 16; u++) {
            xx[u] = *(const float4*)&H1s[h1_unit(e, u)];
            s += xx[u].x + xx[u].y + xx[u].z + xx[u].w;
        }
        float mu = s * (1.f/64.f);
        float vs = 0.f;
        #pragma unroll
        for (int u = 0; u < 16; u++) {
            float d0 = xx[u].x - mu, d1 = xx[u].y - mu;
            float d2 = xx[u].z - mu, d3 = xx[u].w - mu;
            vs += d0*d0 + d1*d1 + d2*d2 + d3*d3;
        }
        float rstd = 1.f / sqrtf(vs * (1.f/64.f) + 1e-5f);
        float acc = 0.f;
        #pragma unroll
        for (int u = 0; u < 16; u++) {
            float4 gv = *(const float4*)&sp_g2[u*4];
            float4 bv = *(const float4*)&sp_be2[u*4];
            float4 wv = *(const float4*)&sp_w3[u*4];
            acc = fmaf(fmaf((xx[u].x - mu)*rstd, gv.x, bv.x), wv.x, acc);
            acc = fmaf(fmaf((xx[u].y - mu)*rstd, gv.y, bv.y), wv.y, acc);
            acc = fmaf(fmaf((xx[u].z - mu)*rstd, gv.z, bv.z), wv.z, acc);
            acc = fmaf(fmaf((xx[u].w - mu)*rstd, gv.w, bv.w), wv.w, acc);
        }
        int c = c_base + e;
        if (c < L)
            g_logits[(b*TT + i)*NSRC + c] = acc + __ldg(&b3[0]);
    }
}

// ---------------- K4: gumbel argmax + scatter 1.0 ----------------
// One warp per (s,b,i) row; argmax over valid c of logits + gumbel.
__global__ void k_argmax(const float* __restrict__ gumbel, float* __restrict__ out)
{
    int row = blockIdx.x * 8 + (threadIdx.x >> 5);
    if (row >= NROWS) return;
    int lane = threadIdx.x & 31;
    int i  = row % TT;
    int sb = row / TT;          // s*8 + b
    int b  = sb & 7;
    int L  = 192 + i;

    const float* lg = g_logits + (size_t)((b*TT + i)) * NSRC;
    const float* gb = gumbel   + (size_t)row * NSRC;

    float best = -__int_as_float(0x7f800000);   // -inf
    int bidx = 0;
    int c = lane;
    for (; c + 32 < L; c += 64) {               // 2-way unroll for MLP
        float v0 = __ldg(&lg[c])      + __ldg(&gb[c]);
        float v1 = __ldg(&lg[c + 32]) + __ldg(&gb[c + 32]);
        if (v0 > best) { best = v0; bidx = c; }
        if (v1 > best) { best = v1; bidx = c + 32; }
    }
    for (; c < L; c += 32) {
        float v = __ldg(&lg[c]) + __ldg(&gb[c]);
        if (v > best) { best = v; bidx = c; }
    }
    #pragma unroll
    for (int o = 16; o; o >>= 1) {
        float ov = __shfl_xor_sync(0xffffffffu, best, o);
        int   oi = __shfl_xor_sync(0xffffffffu, bidx, o);
        if (ov > best || (ov == best && oi < bidx)) { best = ov; bidx = oi; }
    }
    if (lane == 0)
        out[((size_t)(b*NNODE) + 192 + i) * NNODE + bidx] = 1.0f;
}

// ---------------- launch ----------------
extern "C" void kernel_launch(void* const* d_in, const int* in_sizes, int n_in,
                              void* d_out, int out_size)
{
    const float* nodes = (const float*)d_in[0];
    const float* w1    = (const float*)d_in[1];
    const float* b1    = (const float*)d_in[2];
    const float* g1    = (const float*)d_in[3];
    const float* be1   = (const float*)d_in[4];
    const float* w2    = (const float*)d_in[5];
    const float* b2    = (const float*)d_in[6];
    const float* g2    = (const float*)d_in[7];
    const float* be2   = (const float*)d_in[8];
    const float* w3    = (const float*)d_in[9];
    const float* b3    = (const float*)d_in[10];
    const float* gum   = (const float*)d_in[11];
    float* out = (float*)d_out;

    const int smem_bytes = SMEM_FLOATS * (int)sizeof(float);   // 50,944 B
    cudaFuncSetAttribute(k_edges, cudaFuncAttributeMaxDynamicSharedMemorySize, smem_bytes);

    k_precompute<<<96, 256>>>(nodes, w1, b1);
    k_edges<<<dim3(3, TT, BB), 128, smem_bytes>>>(w2, b2, g2, be2, w3, b3, g1, be1);

    cudaMemsetAsync(out, 0, (size_t)out_size * sizeof(float));
    k_argmax<<<NROWS / 8, 256>>>(gum, out);
}

// round 5
// speedup vs baseline: 1.7195x; 1.7195x over previous
#include <cuda_runtime.h>
#include <cstdint>

// Problem constants (static per reference)
#define BB    8
#define NNODE 384
#define FF    64
#define TT    192
#define NSRC  383         // T + TAU - 1
#define NROWS (5*BB*TT)   // S*B*192 = 7680 argmax rows

// ---------------- device scratch (no allocs allowed) ----------------
__device__ float g_P[BB*NNODE*FF];        // nodes @ w1_top + b1  (sink half)
__device__ float g_Q[BB*NNODE*FF];        // nodes @ w1_bot       (src half)
__device__ float g_logits[BB*TT*NSRC];    // per-edge logits, dense (b, i, c)

// XOR swizzle on 16B units within a 64-float row: unit u of row r lives at
// physical unit (u ^ (r & 15)). For any aligned float4 access:
//  - 32 lanes reading/writing 32 distinct rows at the same u -> units
//    (u^r) distinct per octet -> conflict-free
//  - per-lane weight reads w[lane][u]: unit index mod 8 = (u ^ lane) mod 8,
//    distinct per octet -> conflict-free
//  - broadcasts (all lanes same address) trivially conflict-free
__device__ __forceinline__ int swz_u(int row, int u) {
    return row*64 + ((u ^ (row & 15)) << 2);
}
__device__ __forceinline__ int swz_k(int row, int k) {
    return row*64 + ((((k >> 2) ^ (row & 15)) << 2) | (k & 3));
}

// ---------------- K1: factor layer 1 per-node ----------------
// P[b,n,f] = b1[f] + sum_k nodes[b,n,k]*w1[k,f];  Q[b,n,f] = sum_k nodes*w1[64+k,f]
__global__ void k_precompute(const float* __restrict__ nodes,
                             const float* __restrict__ w1,
                             const float* __restrict__ b1)
{
    __shared__ float w1s[128*64];
    __shared__ float nds[4][64];
    int tid = threadIdx.x;
    for (int idx = tid; idx < 128*64; idx += 256) w1s[idx] = w1[idx];
    __syncthreads();
    int f = tid & 63, slot = tid >> 6;
    int row0 = blockIdx.x * 16;                 // 192 blocks * 16 rows = 3072
    for (int r = 0; r < 16; r += 4) {
        int row = row0 + r + slot;
        nds[slot][f] = nodes[row*64 + f];
        __syncthreads();
        float accp = b1[f], accq = 0.f;
        #pragma unroll
        for (int k = 0; k < 64; k++) {
            float nv = nds[slot][k];
            accp = fmaf(nv, w1s[k*64 + f],       accp);
            accq = fmaf(nv, w1s[(64+k)*64 + f],  accq);
        }
        g_P[row*64 + f] = accp;
        g_Q[row*64 + f] = accq;
        __syncthreads();
    }
}

// ---------------- K2: fused edge MLP -> logits ----------------
// 128 threads = 4 warps, 128 edges/block. Warp w owns edges [32w, 32w+32).
// phase1: thread-per-edge LN1 -> swizzled smem H1 row.
// phase2: plain-FFMA GEMM, 8-edge x 2-j register blocking, conflict-free LDS;
//         relu(x+b2) written back into the (dead) H1 rows.
// phase3: thread-per-edge LN2 + w3 dot -> logit.
#define SMEM_FLOATS (8192 + 4096 + 448)
__global__ void __launch_bounds__(128, 4) k_edges(
    const float* __restrict__ w2,  const float* __restrict__ b2,
    const float* __restrict__ g2,  const float* __restrict__ be2,
    const float* __restrict__ w3,  const float* __restrict__ b3,
    const float* __restrict__ g1,  const float* __restrict__ be1)
{
    extern __shared__ float smem[];
    float* H1s   = smem;             // [128 rows][64] swizzled
    float* W2f   = smem + 8192;      // [64 j rows][64] swizzled: (j,u) = w2[4u..4u+3][j]
    float* sp_p  = smem + 12288;     // 64
    float* sp_b2 = sp_p  + 64;
    float* sp_g1 = sp_b2 + 64;
    float* sp_be1= sp_g1 + 64;
    float* sp_g2 = sp_be1+ 64;
    float* sp_be2= sp_g2 + 64;
    float* sp_w3 = sp_be2+ 64;

    int i = blockIdx.y, b = blockIdx.z;
    int sink = 192 + i;
    int L = sink;                       // valid sources: c in [0, sink)
    int c_base = blockIdx.x * 128;
    if (c_base >= L) return;            // uniform early exit

    int tid  = threadIdx.x;
    int lane = tid & 31;
    int w    = tid >> 5;

    // ---- staging: w2 transposed+swizzled, small params ----
    for (int idx = tid; idx < 4096; idx += 128) {
        int j = idx >> 6, rem = idx & 63;
        int u = rem >> 2, t = rem & 3;
        W2f[swz_u(j, u) + t] = w2[(4*u + t)*64 + j];
    }
    if (tid < 64) {
        sp_p[tid]  = g_P[(b*NNODE + sink)*64 + tid];
        sp_b2[tid] = b2[tid];
        sp_g1[tid] = g1[tid];
        sp_be1[tid]= be1[tid];
        sp_g2[tid] = g2[tid];
        sp_be2[tid]= be2[tid];
        sp_w3[tid] = w3[tid];
    }
    __syncthreads();

    // ---- phase 1: thread-per-edge LN1, 64 dims in registers ----
    {
        int e = tid;                          // 0..127 (warp w owns its 32 rows)
        int c = c_base + e;                   // < 384: always safe to read
        const float4* qrow = (const float4*)&g_Q[((b*NNODE) + c)*64];
        float4 x[16];
        float s = 0.f;
        #pragma unroll
        for (int u = 0; u < 16; u++) {
            float4 q = __ldg(&qrow[u]);
            float4 p = *(const float4*)&sp_p[u*4];
            x[u].x = fmaxf(p.x + q.x, 0.f);
            x[u].y = fmaxf(p.y + q.y, 0.f);
            x[u].z = fmaxf(p.z + q.z, 0.f);
            x[u].w = fmaxf(p.w + q.w, 0.f);
            s += x[u].x + x[u].y + x[u].z + x[u].w;
        }
        float mu = s * (1.f/64.f);
        float vs = 0.f;
        #pragma unroll
        for (int u = 0; u < 16; u++) {
            float d0 = x[u].x - mu, d1 = x[u].y - mu;
            float d2 = x[u].z - mu, d3 = x[u].w - mu;
            vs += d0*d0 + d1*d1 + d2*d2 + d3*d3;
        }
        float rstd = 1.f / sqrtf(vs * (1.f/64.f) + 1e-5f);
        #pragma unroll
        for (int u = 0; u < 16; u++) {
            float4 gv = *(const float4*)&sp_g1[u*4];
            float4 bv = *(const float4*)&sp_be1[u*4];
            float4 h;
            h.x = fmaf((x[u].x - mu)*rstd, gv.x, bv.x);
            h.y = fmaf((x[u].y - mu)*rstd, gv.y, bv.y);
            h.z = fmaf((x[u].z - mu)*rstd, gv.z, bv.z);
            h.w = fmaf((x[u].w - mu)*rstd, gv.w, bv.w);
            *(float4*)&H1s[swz_u(e, u)] = h;
        }
    }
    __syncwarp();

    // ---- phase 2: plain-FFMA GEMM, 4 passes of 8 edges per warp ----
    {
        float b2a = sp_b2[lane], b2b = sp_b2[lane + 32];

        #pragma unroll 1
        for (int pass = 0; pass < 4; pass++) {
            int e0 = w*32 + pass*8;
            float accA[8], accB[8];
            #pragma unroll
            for (int ee = 0; ee < 8; ee++) { accA[ee] = 0.f; accB[ee] = 0.f; }

            #pragma unroll
            for (int u = 0; u < 16; u++) {
                float4 wA = *(const float4*)&W2f[swz_u(lane, u)];       // j = lane
                float4 wB = *(const float4*)&W2f[swz_u(lane + 32, u)];  // j = lane+32
                #pragma unroll
                for (int ee = 0; ee < 8; ee++) {
                    float4 h = *(const float4*)&H1s[swz_u(e0 + ee, u)]; // broadcast
                    accA[ee] = fmaf(h.x, wA.x, accA[ee]);
                    accA[ee] = fmaf(h.y, wA.y, accA[ee]);
                    accA[ee] = fmaf(h.z, wA.z, accA[ee]);
                    accA[ee] = fmaf(h.w, wA.w, accA[ee]);
                    accB[ee] = fmaf(h.x, wB.x, accB[ee]);
                    accB[ee] = fmaf(h.y, wB.y, accB[ee]);
                    accB[ee] = fmaf(h.z, wB.z, accB[ee]);
                    accB[ee] = fmaf(h.w, wB.w, accB[ee]);
                }
            }
            __syncwarp();   // all lanes done reading these 8 rows
            #pragma unroll
            for (int ee = 0; ee < 8; ee++) {
                int e = e0 + ee;
                H1s[swz_k(e, lane)]      = fmaxf(accA[ee] + b2a, 0.f);
                H1s[swz_k(e, lane + 32)] = fmaxf(accB[ee] + b2b, 0.f);
            }
        }
    }
    __syncwarp();

    // ---- phase 3: thread-per-edge LN2 + logit ----
    {
        int e = w*32 + lane;                 // row this warp wrote
        float4 xx[16];
        float s = 0.f;
        #pragma unroll
        for (int u = 0; u < 16; u++) {
            xx[u] = *(const float4*)&H1s[swz_u(e, u)];
            s += xx[u].x + xx[u].y + xx[u].z + xx[u].w;
        }
        float mu = s * (1.f/64.f);
        float vs = 0.f;
        #pragma unroll
        for (int u = 0; u < 16; u++) {
            float d0 = xx[u].x - mu, d1 = xx[u].y - mu;
            float d2 = xx[u].z - mu, d3 = xx[u].w - mu;
            vs += d0*d0 + d1*d1 + d2*d2 + d3*d3;
        }
        float rstd = 1.f / sqrtf(vs * (1.f/64.f) + 1e-5f);
        float acc = 0.f;
        #pragma unroll
        for (int u = 0; u < 16; u++) {
            float4 gv = *(const float4*)&sp_g2[u*4];
            float4 bv = *(const float4*)&sp_be2[u*4];
            float4 wv = *(const float4*)&sp_w3[u*4];
            acc = fmaf(fmaf((xx[u].x - mu)*rstd, gv.x, bv.x), wv.x, acc);
            acc = fmaf(fmaf((xx[u].y - mu)*rstd, gv.y, bv.y), wv.y, acc);
            acc = fmaf(fmaf((xx[u].z - mu)*rstd, gv.z, bv.z), wv.z, acc);
            acc = fmaf(fmaf((xx[u].w - mu)*rstd, gv.w, bv.w), wv.w, acc);
        }
        int c = c_base + e;
        if (c < L)
            g_logits[(b*TT + i)*NSRC + c] = acc + __ldg(&b3[0]);
    }
}

// ---------------- K4: gumbel argmax + scatter 1.0 ----------------
__global__ void k_argmax(const float* __restrict__ gumbel, float* __restrict__ out)
{
    int row = blockIdx.x * 8 + (threadIdx.x >> 5);
    if (row >= NROWS) return;
    int lane = threadIdx.x & 31;
    int i  = row % TT;
    int sb = row / TT;          // s*8 + b
    int b  = sb & 7;
    int L  = 192 + i;

    const float* lg = g_logits + (size_t)((b*TT + i)) * NSRC;
    const float* gb = gumbel   + (size_t)row * NSRC;

    float best = -__int_as_float(0x7f800000);   // -inf
    int bidx = 0;
    int c = lane;
    for (; c + 32 < L; c += 64) {
        float v0 = __ldg(&lg[c])      + __ldg(&gb[c]);
        float v1 = __ldg(&lg[c + 32]) + __ldg(&gb[c + 32]);
        if (v0 > best) { best = v0; bidx = c; }
        if (v1 > best) { best = v1; bidx = c + 32; }
    }
    for (; c < L; c += 32) {
        float v = __ldg(&lg[c]) + __ldg(&gb[c]);
        if (v > best) { best = v; bidx = c; }
    }
    #pragma unroll
    for (int o = 16; o; o >>= 1) {
        float ov = __shfl_xor_sync(0xffffffffu, best, o);
        int   oi = __shfl_xor_sync(0xffffffffu, bidx, o);
        if (ov > best || (ov == best && oi < bidx)) { best = ov; bidx = oi; }
    }
    if (lane == 0)
        out[((size_t)(b*NNODE) + 192 + i) * NNODE + bidx] = 1.0f;
}

// ---------------- launch ----------------
extern "C" void kernel_launch(void* const* d_in, const int* in_sizes, int n_in,
                              void* d_out, int out_size)
{
    const float* nodes = (const float*)d_in[0];
    const float* w1    = (const float*)d_in[1];
    const float* b1    = (const float*)d_in[2];
    const float* g1    = (const float*)d_in[3];
    const float* be1   = (const float*)d_in[4];
    const float* w2    = (const float*)d_in[5];
    const float* b2    = (const float*)d_in[6];
    const float* g2    = (const float*)d_in[7];
    const float* be2   = (const float*)d_in[8];
    const float* w3    = (const float*)d_in[9];
    const float* b3    = (const float*)d_in[10];
    const float* gum   = (const float*)d_in[11];
    float* out = (float*)d_out;

    const int smem_bytes = SMEM_FLOATS * (int)sizeof(float);   // 50,944 B
    cudaFuncSetAttribute(k_edges, cudaFuncAttributeMaxDynamicSharedMemorySize, smem_bytes);

    k_precompute<<<192, 256>>>(nodes, w1, b1);
    k_edges<<<dim3(3, TT, BB), 128, smem_bytes>>>(w2, b2, g2, be2, w3, b3, g1, be1);

    cudaMemsetAsync(out, 0, (size_t)out_size * sizeof(float));
    k_argmax<<<NROWS / 8, 256>>>(gum, out);
}

// round 7
// speedup vs baseline: 2.8094x; 1.6338x over previous
#include <cuda_runtime.h>
#include <cuda_bf16.h>
#include <cstdint>

// Problem constants (static per reference)
#define BB    8
#define NNODE 384
#define FF    64
#define TT    192
#define NSRC  383         // T + TAU - 1
#define NROWS (5*BB*TT)   // S*B*192 = 7680 argmax rows

// ---------------- device scratch (no allocs allowed) ----------------
__device__ float g_P[BB*NNODE*FF];                 // nodes @ w1_top + b1
__device__ float g_Q[BB*NNODE*FF];                 // nodes @ w1_bot
__device__ float g_logits[BB*TT*NSRC];             // per-edge logits
__device__ __nv_bfloat16 g_w2split[3*64*64];       // [plane][j][k] = split_p(w2[k][j])

// ---------------- helpers ----------------
// exact 3-way bf16 split of fp32: v = hi + mid + lo + O(2^-27 * v)
__device__ __forceinline__ void split3(float v, __nv_bfloat16& hi,
                                       __nv_bfloat16& mid, __nv_bfloat16& lo) {
    hi = __float2bfloat16_rn(v);
    float r1 = v - __bfloat162float(hi);       // exact
    mid = __float2bfloat16_rn(r1);
    float r2 = r1 - __bfloat162float(mid);     // exact
    lo = __float2bfloat16_rn(r2);
}
__device__ __forceinline__ uint32_t pack_bf2(__nv_bfloat16 a, __nv_bfloat16 b) {
    __nv_bfloat162 t(a, b);                    // a = low half (even k)
    return *reinterpret_cast<uint32_t*>(&t);
}
// swizzled byte offset of element (row r, col k) in a bf16 plane with 128B rows:
// 16B units, physical unit = (k>>3) ^ (r&7)
__device__ __forceinline__ int swzb(int r, int k) {
    return r*128 + ((((k >> 3) ^ (r & 7)) << 4) | ((k & 7) << 1));
}
// m16n8k16 row.col f32.bf16.bf16.f32 (plain sm_80+ PTX; HMMA on sm_103a)
__device__ __forceinline__ void mma16816(float* c, const uint32_t* a,
                                         uint32_t b0, uint32_t b1) {
    asm volatile(
        "mma.sync.aligned.m16n8k16.row.col.f32.bf16.bf16.f32 "
        "{%0,%1,%2,%3}, {%4,%5,%6,%7}, {%8,%9}, {%0,%1,%2,%3};"
        : "+f"(c[0]), "+f"(c[1]), "+f"(c[2]), "+f"(c[3])
        : "r"(a[0]), "r"(a[1]), "r"(a[2]), "r"(a[3]), "r"(b0), "r"(b1));
}

// ---------------- K_split: pre-split w2^T into 3 bf16 planes ----------------
__global__ void k_splitw2(const float* __restrict__ w2)
{
    int idx = blockIdx.x * 256 + threadIdx.x;   // 4096 = [j][k]
    int j = idx >> 6, k = idx & 63;
    float v = w2[k*64 + j];
    __nv_bfloat16 hi, mid, lo;
    split3(v, hi, mid, lo);
    g_w2split[idx]        = hi;
    g_w2split[4096 + idx] = mid;
    g_w2split[8192 + idx] = lo;
}

// ---------------- K1: factor layer 1 per-node ----------------
__global__ void k_precompute(const float* __restrict__ nodes,
                             const float* __restrict__ w1,
                             const float* __restrict__ b1)
{
    __shared__ float w1s[128*64];
    __shared__ float nds[4][64];
    int tid = threadIdx.x;
    for (int idx = tid; idx < 128*64; idx += 256) w1s[idx] = w1[idx];
    __syncthreads();
    int f = tid & 63, slot = tid >> 6;
    int row0 = blockIdx.x * 8;                  // 384 blocks * 8 rows = 3072
    for (int r = 0; r < 8; r += 4) {
        int row = row0 + r + slot;
        nds[slot][f] = nodes[row*64 + f];
        __syncthreads();
        float accp = b1[f], accq = 0.f;
        #pragma unroll
        for (int k = 0; k < 64; k++) {
            float nv = nds[slot][k];
            accp = fmaf(nv, w1s[k*64 + f],       accp);
            accq = fmaf(nv, w1s[(64+k)*64 + f],  accq);
        }
        g_P[row*64 + f] = accp;
        g_Q[row*64 + f] = accq;
        __syncthreads();
    }
}

// ---------------- K2: fused edge MLP via mma.sync bf16x3 ----------------
// 128 threads, 128 edges/block. phase1: thread-per-edge LN1 + 3-way bf16
// split -> swizzled smem A planes. GEMM: per warp (32 edges) 6 split-products
// x 4 k16-steps x 2 m16 x 8 n8 HMMA, fp32 accums in registers. Epilogue:
// relu+LN2 with quad (4-lane) shfl reductions -> logits. No tcgen05.
#define A_BASE   2048
#define B_BASE   (A_BASE + 3*16384)          // 51200
#define SMEM_BYTES (B_BASE + 3*8192)         // 75776
__global__ void __launch_bounds__(128, 3) k_edges(
    const float* __restrict__ b2, const float* __restrict__ g2,
    const float* __restrict__ be2, const float* __restrict__ w3,
    const float* __restrict__ b3, const float* __restrict__ g1,
    const float* __restrict__ be1)
{
    extern __shared__ __align__(128) char smem[];
    float* smf    = (float*)smem;
    float* sp_p   = smf;                     // 7x64 param block (1792B < 2048)
    float* sp_g1  = sp_p  + 64;
    float* sp_be1 = sp_g1 + 64;
    float* sp_b2  = sp_be1+ 64;
    float* sp_g2  = sp_b2 + 64;
    float* sp_be2 = sp_g2 + 64;
    float* sp_w3  = sp_be2+ 64;

    int i = blockIdx.y, b = blockIdx.z;
    int sink = 192 + i;
    int L = sink;
    int c_base = blockIdx.x * 128;
    if (c_base >= L) return;                 // uniform early exit (before syncs)

    int tid  = threadIdx.x;
    int lane = tid & 31;
    int w    = tid >> 5;

    // stage B planes (pre-split w2^T), swizzled: 1536 uint4
    {
        const uint4* src = (const uint4*)g_w2split;
        for (int idx = tid; idx < 1536; idx += 128) {
            int p = idx >> 9, q = idx & 511;
            int j = q >> 3, u = q & 7;
            *(uint4*)(smem + B_BASE + p*8192 + j*128 + ((u ^ (j & 7)) << 4)) = src[idx];
        }
    }
    if (tid < 64) {
        sp_p[tid]  = g_P[(b*NNODE + sink)*64 + tid];
        sp_g1[tid] = g1[tid];
        sp_be1[tid]= be1[tid];
        sp_b2[tid] = b2[tid];
        sp_g2[tid] = g2[tid];
        sp_be2[tid]= be2[tid];
        sp_w3[tid] = w3[tid];
    }
    __syncthreads();

    // ---- phase 1: thread-per-edge LN1 + split -> A planes ----
    {
        int e = tid;
        int c = c_base + e;                  // < 384: safe read
        const float4* qrow = (const float4*)&g_Q[((b*NNODE) + c)*64];
        float4 x[16];
        float s = 0.f;
        #pragma unroll
        for (int u = 0; u < 16; u++) {
            float4 q = __ldg(&qrow[u]);
            float4 p = *(const float4*)&sp_p[u*4];
            x[u].x = fmaxf(p.x + q.x, 0.f);
            x[u].y = fmaxf(p.y + q.y, 0.f);
            x[u].z = fmaxf(p.z + q.z, 0.f);
            x[u].w = fmaxf(p.w + q.w, 0.f);
            s += x[u].x + x[u].y + x[u].z + x[u].w;
        }
        float mu = s * (1.f/64.f);
        float vs = 0.f;
        #pragma unroll
        for (int u = 0; u < 16; u++) {
            float d0 = x[u].x - mu, d1 = x[u].y - mu;
            float d2 = x[u].z - mu, d3 = x[u].w - mu;
            vs += d0*d0 + d1*d1 + d2*d2 + d3*d3;
        }
        float rstd = 1.f / sqrtf(vs * (1.f/64.f) + 1e-5f);
        #pragma unroll
        for (int u = 0; u < 16; u++) {
            float4 gv = *(const float4*)&sp_g1[u*4];
            float4 bv = *(const float4*)&sp_be1[u*4];
            x[u].x = fmaf((x[u].x - mu)*rstd, gv.x, bv.x);
            x[u].y = fmaf((x[u].y - mu)*rstd, gv.y, bv.y);
            x[u].z = fmaf((x[u].z - mu)*rstd, gv.z, bv.z);
            x[u].w = fmaf((x[u].w - mu)*rstd, gv.w, bv.w);
        }
        int rowoff = e * 128;
        #pragma unroll
        for (int u2 = 0; u2 < 8; u2++) {
            float4 a0 = x[2*u2], a1 = x[2*u2 + 1];
            float vv[8] = {a0.x, a0.y, a0.z, a0.w, a1.x, a1.y, a1.z, a1.w};
            __nv_bfloat16 h[8], m[8], l[8];
            #pragma unroll
            for (int t = 0; t < 8; t++) split3(vv[t], h[t], m[t], l[t]);
            uint4 uh = make_uint4(pack_bf2(h[0],h[1]), pack_bf2(h[2],h[3]),
                                  pack_bf2(h[4],h[5]), pack_bf2(h[6],h[7]));
            uint4 um = make_uint4(pack_bf2(m[0],m[1]), pack_bf2(m[2],m[3]),
                                  pack_bf2(m[4],m[5]), pack_bf2(m[6],m[7]));
            uint4 ul = make_uint4(pack_bf2(l[0],l[1]), pack_bf2(l[2],l[3]),
                                  pack_bf2(l[4],l[5]), pack_bf2(l[6],l[7]));
            int phys = rowoff + ((u2 ^ (e & 7)) << 4);
            *(uint4*)(smem + A_BASE           + phys) = uh;
            *(uint4*)(smem + A_BASE + 16384   + phys) = um;
            *(uint4*)(smem + A_BASE + 2*16384 + phys) = ul;
        }
    }
    __syncthreads();

    // ---- phase 2: HMMA GEMM. warp w owns edges [32w, 32w+32) ----
    int e0 = w * 32;
    int q  = lane >> 2;          // fragment row group
    int kq = (lane & 3) * 2;     // fragment col pair

    float acc[2][8][4];
    #pragma unroll
    for (int mt = 0; mt < 2; mt++)
        #pragma unroll
        for (int nt = 0; nt < 8; nt++)
            #pragma unroll
            for (int t = 0; t < 4; t++) acc[mt][nt][t] = 0.f;

    const int pa[6] = {0, 0, 1, 1, 0, 2};    // hh, hm, mh, hl(?)... A planes
    const int pb[6] = {0, 1, 0, 1, 2, 0};    // pairs: hh,hm,mh,mm? -> see note
    // products: (h,h) (h,m) (m,h) (m,m) (h,l) (l,h): err ~2^-27
    // pa/pb above: p3=(1,1)=mm, p4=(0,2)=hl, p5=(2,0)=lh. correct set.

    #pragma unroll 1
    for (int p = 0; p < 6; p++) {
        const char* Ap = smem + A_BASE + pa[p]*16384;
        const char* Bp = smem + B_BASE + pb[p]*8192;
        #pragma unroll
        for (int ks = 0; ks < 4; ks++) {
            int k0 = ks*16 + kq;
            int k1 = k0 + 8;
            uint32_t a[2][4];
            #pragma unroll
            for (int mt = 0; mt < 2; mt++) {
                int r0 = e0 + mt*16 + q, r1 = r0 + 8;
                a[mt][0] = *(const uint32_t*)(Ap + swzb(r0, k0));
                a[mt][1] = *(const uint32_t*)(Ap + swzb(r1, k0));
                a[mt][2] = *(const uint32_t*)(Ap + swzb(r0, k1));
                a[mt][3] = *(const uint32_t*)(Ap + swzb(r1, k1));
            }
            #pragma unroll
            for (int nt = 0; nt < 8; nt++) {
                int j = nt*8 + q;
                uint32_t b0 = *(const uint32_t*)(Bp + swzb(j, k0));
                uint32_t b1 = *(const uint32_t*)(Bp + swzb(j, k1));
                mma16816(acc[0][nt], a[0], b0, b1);
                mma16816(acc[1][nt], a[1], b0, b1);
            }
        }
    }

    // ---- epilogue: relu + LN2 via quad reductions -> logits ----
    {
        float2 pb2[8], pg2[8], pbe2[8], pw3[8];
        #pragma unroll
        for (int nt = 0; nt < 8; nt++) {
            int jc = nt*8 + kq;
            pb2[nt]  = *(const float2*)&sp_b2[jc];
            pg2[nt]  = *(const float2*)&sp_g2[jc];
            pbe2[nt] = *(const float2*)&sp_be2[jc];
            pw3[nt]  = *(const float2*)&sp_w3[jc];
        }
        float b3v = __ldg(&b3[0]);
        float* lrow = g_logits + (b*TT + i)*NSRC;

        #pragma unroll
        for (int mt = 0; mt < 2; mt++) {
            // rows rA = e0 + mt*16 + q, rB = rA + 8; thread holds 16 cols each
            float xA[16], xB[16];
            float sA = 0.f, sB = 0.f;
            #pragma unroll
            for (int nt = 0; nt < 8; nt++) {
                xA[2*nt]   = fmaxf(acc[mt][nt][0] + pb2[nt].x, 0.f);
                xA[2*nt+1] = fmaxf(acc[mt][nt][1] + pb2[nt].y, 0.f);
                xB[2*nt]   = fmaxf(acc[mt][nt][2] + pb2[nt].x, 0.f);
                xB[2*nt+1] = fmaxf(acc[mt][nt][3] + pb2[nt].y, 0.f);
                sA += xA[2*nt] + xA[2*nt+1];
                sB += xB[2*nt] + xB[2*nt+1];
            }
            sA += __shfl_xor_sync(0xffffffffu, sA, 1);
            sA += __shfl_xor_sync(0xffffffffu, sA, 2);
            sB += __shfl_xor_sync(0xffffffffu, sB, 1);
            sB += __shfl_xor_sync(0xffffffffu, sB, 2);
            float muA = sA * (1.f/64.f), muB = sB * (1.f/64.f);
            float vA = 0.f, vB = 0.f;
            #pragma unroll
            for (int t = 0; t < 16; t++) {
                float dA = xA[t] - muA; vA += dA*dA;
                float dB = xB[t] - muB; vB += dB*dB;
            }
            vA += __shfl_xor_sync(0xffffffffu, vA, 1);
            vA += __shfl_xor_sync(0xffffffffu, vA, 2);
            vB += __shfl_xor_sync(0xffffffffu, vB, 1);
            vB += __shfl_xor_sync(0xffffffffu, vB, 2);
            float rsA = 1.f / sqrtf(vA * (1.f/64.f) + 1e-5f);
            float rsB = 1.f / sqrtf(vB * (1.f/64.f) + 1e-5f);
            float dA = 0.f, dB = 0.f;
            #pragma unroll
            for (int nt = 0; nt < 8; nt++) {
                dA = fmaf(fmaf((xA[2*nt]   - muA)*rsA, pg2[nt].x, pbe2[nt].x), pw3[nt].x, dA);
                dA = fmaf(fmaf((xA[2*nt+1] - muA)*rsA, pg2[nt].y, pbe2[nt].y), pw3[nt].y, dA);
                dB = fmaf(fmaf((xB[2*nt]   - muB)*rsB, pg2[nt].x, pbe2[nt].x), pw3[nt].x, dB);
                dB = fmaf(fmaf((xB[2*nt+1] - muB)*rsB, pg2[nt].y, pbe2[nt].y), pw3[nt].y, dB);
            }
            dA += __shfl_xor_sync(0xffffffffu, dA, 1);
            dA += __shfl_xor_sync(0xffffffffu, dA, 2);
            dB += __shfl_xor_sync(0xffffffffu, dB, 1);
            dB += __shfl_xor_sync(0xffffffffu, dB, 2);
            if ((lane & 3) == 0) {
                int eA = e0 + mt*16 + q;
                int cA = c_base + eA;
                if (cA < L)     lrow[cA]     = dA + b3v;
                int cB = cA + 8;
                if (cB < L)     lrow[cB]     = dB + b3v;
            }
        }
    }
}

// ---------------- K4: gumbel argmax + scatter 1.0 ----------------
__global__ void k_argmax(const float* __restrict__ gumbel, float* __restrict__ out)
{
    int row = blockIdx.x * 8 + (threadIdx.x >> 5);
    if (row >= NROWS) return;
    int lane = threadIdx.x & 31;
    int i  = row % TT;
    int sb = row / TT;
    int b  = sb & 7;
    int L  = 192 + i;

    const float* lg = g_logits + (size_t)((b*TT + i)) * NSRC;
    const float* gb = gumbel   + (size_t)row * NSRC;

    float best = -__int_as_float(0x7f800000);
    int bidx = 0;
    int c = lane;
    for (; c + 32 < L; c += 64) {
        float v0 = __ldg(&lg[c])      + __ldg(&gb[c]);
        float v1 = __ldg(&lg[c + 32]) + __ldg(&gb[c + 32]);
        if (v0 > best) { best = v0; bidx = c; }
        if (v1 > best) { best = v1; bidx = c + 32; }
    }
    for (; c < L; c += 32) {
        float v = __ldg(&lg[c]) + __ldg(&gb[c]);
        if (v > best) { best = v; bidx = c; }
    }
    #pragma unroll
    for (int o = 16; o; o >>= 1) {
        float ov = __shfl_xor_sync(0xffffffffu, best, o);
        int   oi = __shfl_xor_sync(0xffffffffu, bidx, o);
        if (ov > best || (ov == best && oi < bidx)) { best = ov; bidx = oi; }
    }
    if (lane == 0)
        out[((size_t)(b*NNODE) + 192 + i) * NNODE + bidx] = 1.0f;
}

// ---------------- launch ----------------
extern "C" void kernel_launch(void* const* d_in, const int* in_sizes, int n_in,
                              void* d_out, int out_size)
{
    const float* nodes = (const float*)d_in[0];
    const float* w1    = (const float*)d_in[1];
    const float* b1    = (const float*)d_in[2];
    const float* g1    = (const float*)d_in[3];
    const float* be1   = (const float*)d_in[4];
    const float* w2    = (const float*)d_in[5];
    const float* b2    = (const float*)d_in[6];
    const float* g2    = (const float*)d_in[7];
    const float* be2   = (const float*)d_in[8];
    const float* w3    = (const float*)d_in[9];
    const float* b3    = (const float*)d_in[10];
    const float* gum   = (const float*)d_in[11];
    float* out = (float*)d_out;

    cudaFuncSetAttribute(k_edges, cudaFuncAttributeMaxDynamicSharedMemorySize,
                         SMEM_BYTES);

    k_splitw2<<<16, 256>>>(w2);
    k_precompute<<<384, 256>>>(nodes, w1, b1);
    cudaMemsetAsync(out, 0, (size_t)out_size * sizeof(float));
    k_edges<<<dim3(3, TT, BB), 128, SMEM_BYTES>>>(b2, g2, be2, w3, b3, g1, be1);
    k_argmax<<<NROWS / 8, 256>>>(gum, out);
}

// round 8
// speedup vs baseline: 4.0062x; 1.4260x over previous
#include <cuda_runtime.h>
#include <cuda_fp16.h>
#include <cstdint>

// Problem constants (static per reference)
#define BB    8
#define NNODE 384
#define FF    64
#define TT    192
#define NSRC  383         // T + TAU - 1
#define NROWS (5*BB*TT)   // S*B*192 = 7680 argmax rows

// ---------------- device scratch (no allocs allowed) ----------------
__device__ float g_P[BB*NNODE*FF];          // nodes @ w1_top + b1
__device__ float g_Q[BB*NNODE*FF];          // nodes @ w1_bot
__device__ float g_logits[BB*TT*NSRC];      // per-edge logits
__device__ __half g_w2split[2*64*64];       // [plane][j][k] = split_p(w2[k][j])
__device__ float g_sinkv;                   // dummy target (never written)

// ---------------- helpers ----------------
// exact 2-way fp16 split of fp32: v = h + m + r, |r| <= 2^-24 |v|
__device__ __forceinline__ void split2(float v, __half& h, __half& m) {
    h = __float2half_rn(v);
    float r1 = v - __half2float(h);        // exact
    m = __float2half_rn(r1);
}
__device__ __forceinline__ uint32_t pack_h2(__half a, __half b) {
    __half2 t = __halves2half2(a, b);      // a = low half (even k)
    return *reinterpret_cast<uint32_t*>(&t);
}
// swizzled byte offset of fp16 element (row r, col k), 128B rows, 16B units:
// physical unit = (k>>3) ^ (r&7)
__device__ __forceinline__ int swzb(int r, int k) {
    return r*128 + ((((k >> 3) ^ (r & 7)) << 4) | ((k & 7) << 1));
}
// m16n8k16 row.col f32.f16.f16.f32 (plain sm_80+ PTX; HMMA on sm_103a)
__device__ __forceinline__ void mma16816(float* c, const uint32_t* a,
                                         uint32_t b0, uint32_t b1) {
    asm volatile(
        "mma.sync.aligned.m16n8k16.row.col.f32.f16.f16.f32 "
        "{%0,%1,%2,%3}, {%4,%5,%6,%7}, {%8,%9}, {%0,%1,%2,%3};"
        : "+f"(c[0]), "+f"(c[1]), "+f"(c[2]), "+f"(c[3])
        : "r"(a[0]), "r"(a[1]), "r"(a[2]), "r"(a[3]), "r"(b0), "r"(b1));
}

// ---------------- dummies (ncu -s 5 slot alignment onto k_edges) ----------
__global__ void k_dummy() { if (threadIdx.x > 1024) g_sinkv = 1.f; }

// ---------------- K_split: pre-split w2^T into 2 fp16 planes -------------
__global__ void k_splitw2(const float* __restrict__ w2)
{
    int idx = blockIdx.x * 256 + threadIdx.x;   // 4096 = [j][k]
    int j = idx >> 6, k = idx & 63;
    float v = w2[k*64 + j];
    __half h, m;
    split2(v, h, m);
    g_w2split[idx]        = h;
    g_w2split[4096 + idx] = m;
}

// ---------------- K1: factor layer 1 per-node ----------------
__global__ void k_precompute(const float* __restrict__ nodes,
                             const float* __restrict__ w1,
                             const float* __restrict__ b1)
{
    __shared__ float w1s[128*64];
    __shared__ float nds[4][64];
    int tid = threadIdx.x;
    // stage w1 as float4 (8 per thread)
    {
        const float4* src = (const float4*)w1;
        float4* dst = (float4*)w1s;
        #pragma unroll
        for (int t = 0; t < 8; t++) dst[tid + 256*t] = src[tid + 256*t];
    }
    __syncthreads();
    int f = tid & 63, slot = tid >> 6;
    int row0 = blockIdx.x * 12;                 // 256 blocks * 12 rows = 3072
    for (int r = 0; r < 12; r += 4) {
        int row = row0 + r + slot;
        nds[slot][f] = nodes[row*64 + f];
        __syncthreads();
        float accp = b1[f], accq = 0.f;
        #pragma unroll
        for (int k = 0; k < 64; k++) {
            float nv = nds[slot][k];
            accp = fmaf(nv, w1s[k*64 + f],       accp);
            accq = fmaf(nv, w1s[(64+k)*64 + f],  accq);
        }
        g_P[row*64 + f] = accp;
        g_Q[row*64 + f] = accq;
        __syncthreads();
    }
}

// ---------------- K2: fused edge MLP via mma.sync fp16x2 ----------------
// 128 threads, 128 edges/block. phase1: thread-per-edge LN1 + 2-way fp16
// split -> swizzled smem A planes (h, m). GEMM per warp (32 edges):
// 3 products {AhBh, AhBm, AmBh} x 4 k16-steps x 2 m16 x 8 n8 HMMA, both A
// and B fragments hoisted per k-step (192 LDS, 192 HMMA per warp).
// Epilogue: relu+LN2 with quad shfl reductions -> logits.
#define A_BASE   2048
#define B_BASE   (A_BASE + 2*16384)          // 34816
#define SMEM_BYTES (B_BASE + 2*8192)         // 51200
__global__ void __launch_bounds__(128, 3) k_edges(
    const float* __restrict__ b2, const float* __restrict__ g2,
    const float* __restrict__ be2, const float* __restrict__ w3,
    const float* __restrict__ b3, const float* __restrict__ g1,
    const float* __restrict__ be1)
{
    extern __shared__ __align__(128) char smem[];
    float* smf    = (float*)smem;
    float* sp_p   = smf;                     // 7x64 param block (1792B < 2048)
    float* sp_g1  = sp_p  + 64;
    float* sp_be1 = sp_g1 + 64;
    float* sp_b2  = sp_be1+ 64;
    float* sp_g2  = sp_b2 + 64;
    float* sp_be2 = sp_g2 + 64;
    float* sp_w3  = sp_be2+ 64;

    int i = blockIdx.y, b = blockIdx.z;
    int sink = 192 + i;
    int L = sink;
    int c_base = blockIdx.x * 128;
    if (c_base >= L) return;                 // uniform early exit (before syncs)

    int tid  = threadIdx.x;
    int lane = tid & 31;
    int w    = tid >> 5;

    // stage B planes (pre-split fp16 w2^T), swizzled: 1024 uint4
    {
        const uint4* src = (const uint4*)g_w2split;
        for (int idx = tid; idx < 1024; idx += 128) {
            int p = idx >> 9, q = idx & 511;
            int j = q >> 3, u = q & 7;
            *(uint4*)(smem + B_BASE + p*8192 + j*128 + ((u ^ (j & 7)) << 4)) = src[idx];
        }
    }
    if (tid < 64) {
        sp_p[tid]  = g_P[(b*NNODE + sink)*64 + tid];
        sp_g1[tid] = g1[tid];
        sp_be1[tid]= be1[tid];
        sp_b2[tid] = b2[tid];
        sp_g2[tid] = g2[tid];
        sp_be2[tid]= be2[tid];
        sp_w3[tid] = w3[tid];
    }
    __syncthreads();

    // ---- phase 1: thread-per-edge LN1 + fp16 split -> A planes ----
    {
        int e = tid;
        int c = c_base + e;                  // < 384: safe read
        const float4* qrow = (const float4*)&g_Q[((b*NNODE) + c)*64];
        float4 x[16];
        float s = 0.f;
        #pragma unroll
        for (int u = 0; u < 16; u++) {
            float4 q = __ldg(&qrow[u]);
            float4 p = *(const float4*)&sp_p[u*4];
            x[u].x = fmaxf(p.x + q.x, 0.f);
            x[u].y = fmaxf(p.y + q.y, 0.f);
            x[u].z = fmaxf(p.z + q.z, 0.f);
            x[u].w = fmaxf(p.w + q.w, 0.f);
            s += x[u].x + x[u].y + x[u].z + x[u].w;
        }
        float mu = s * (1.f/64.f);
        float vs = 0.f;
        #pragma unroll
        for (int u = 0; u < 16; u++) {
            float d0 = x[u].x - mu, d1 = x[u].y - mu;
            float d2 = x[u].z - mu, d3 = x[u].w - mu;
            vs += d0*d0 + d1*d1 + d2*d2 + d3*d3;
        }
        float rstd = 1.f / sqrtf(vs * (1.f/64.f) + 1e-5f);
        #pragma unroll
        for (int u = 0; u < 16; u++) {
            float4 gv = *(const float4*)&sp_g1[u*4];
            float4 bv = *(const float4*)&sp_be1[u*4];
            x[u].x = fmaf((x[u].x - mu)*rstd, gv.x, bv.x);
            x[u].y = fmaf((x[u].y - mu)*rstd, gv.y, bv.y);
            x[u].z = fmaf((x[u].z - mu)*rstd, gv.z, bv.z);
            x[u].w = fmaf((x[u].w - mu)*rstd, gv.w, bv.w);
        }
        int rowoff = e * 128;
        #pragma unroll
        for (int u2 = 0; u2 < 8; u2++) {
            float4 a0 = x[2*u2], a1 = x[2*u2 + 1];
            float vv[8] = {a0.x, a0.y, a0.z, a0.w, a1.x, a1.y, a1.z, a1.w};
            __half h[8], m[8];
            #pragma unroll
            for (int t = 0; t < 8; t++) split2(vv[t], h[t], m[t]);
            uint4 uh = make_uint4(pack_h2(h[0],h[1]), pack_h2(h[2],h[3]),
                                  pack_h2(h[4],h[5]), pack_h2(h[6],h[7]));
            uint4 um = make_uint4(pack_h2(m[0],m[1]), pack_h2(m[2],m[3]),
                                  pack_h2(m[4],m[5]), pack_h2(m[6],m[7]));
            int phys = rowoff + ((u2 ^ (e & 7)) << 4);
            *(uint4*)(smem + A_BASE         + phys) = uh;
            *(uint4*)(smem + A_BASE + 16384 + phys) = um;
        }
    }
    __syncthreads();

    // ---- phase 2: HMMA GEMM, 3 products, ks-outer with hoisted frags ----
    int e0 = w * 32;
    int q  = lane >> 2;          // fragment row group
    int kq = (lane & 3) * 2;     // fragment col pair

    float acc[2][8][4];
    #pragma unroll
    for (int mt = 0; mt < 2; mt++)
        #pragma unroll
        for (int nt = 0; nt < 8; nt++)
            #pragma unroll
            for (int t = 0; t < 4; t++) acc[mt][nt][t] = 0.f;

    const char* Ah = smem + A_BASE;
    const char* Am = smem + A_BASE + 16384;
    const char* Bh = smem + B_BASE;
    const char* Bm = smem + B_BASE + 8192;

    #pragma unroll
    for (int ks = 0; ks < 4; ks++) {
        int k0 = ks*16 + kq;
        int k1 = k0 + 8;
        uint32_t ah[2][4], am[2][4];
        #pragma unroll
        for (int mt = 0; mt < 2; mt++) {
            int r0 = e0 + mt*16 + q, r1 = r0 + 8;
            ah[mt][0] = *(const uint32_t*)(Ah + swzb(r0, k0));
            ah[mt][1] = *(const uint32_t*)(Ah + swzb(r1, k0));
            ah[mt][2] = *(const uint32_t*)(Ah + swzb(r0, k1));
            ah[mt][3] = *(const uint32_t*)(Ah + swzb(r1, k1));
            am[mt][0] = *(const uint32_t*)(Am + swzb(r0, k0));
            am[mt][1] = *(const uint32_t*)(Am + swzb(r1, k0));
            am[mt][2] = *(const uint32_t*)(Am + swzb(r0, k1));
            am[mt][3] = *(const uint32_t*)(Am + swzb(r1, k1));
        }
        uint32_t bh[8][2], bm[8][2];
        #pragma unroll
        for (int nt = 0; nt < 8; nt++) {
            int j = nt*8 + q;
            bh[nt][0] = *(const uint32_t*)(Bh + swzb(j, k0));
            bh[nt][1] = *(const uint32_t*)(Bh + swzb(j, k1));
            bm[nt][0] = *(const uint32_t*)(Bm + swzb(j, k0));
            bm[nt][1] = *(const uint32_t*)(Bm + swzb(j, k1));
        }
        #pragma unroll
        for (int nt = 0; nt < 8; nt++) {
            mma16816(acc[0][nt], ah[0], bh[nt][0], bh[nt][1]);   // h*h
            mma16816(acc[1][nt], ah[1], bh[nt][0], bh[nt][1]);
            mma16816(acc[0][nt], ah[0], bm[nt][0], bm[nt][1]);   // h*m
            mma16816(acc[1][nt], ah[1], bm[nt][0], bm[nt][1]);
            mma16816(acc[0][nt], am[0], bh[nt][0], bh[nt][1]);   // m*h
            mma16816(acc[1][nt], am[1], bh[nt][0], bh[nt][1]);
        }
    }

    // ---- epilogue: relu + LN2 via quad reductions -> logits ----
    {
        float2 pb2[8], pg2[8], pbe2[8], pw3[8];
        #pragma unroll
        for (int nt = 0; nt < 8; nt++) {
            int jc = nt*8 + kq;
            pb2[nt]  = *(const float2*)&sp_b2[jc];
            pg2[nt]  = *(const float2*)&sp_g2[jc];
            pbe2[nt] = *(const float2*)&sp_be2[jc];
            pw3[nt]  = *(const float2*)&sp_w3[jc];
        }
        float b3v = __ldg(&b3[0]);
        float* lrow = g_logits + (b*TT + i)*NSRC;

        #pragma unroll
        for (int mt = 0; mt < 2; mt++) {
            // rows rA = e0 + mt*16 + q, rB = rA + 8; thread holds 16 cols each
            float xA[16], xB[16];
            float sA = 0.f, sB = 0.f;
            #pragma unroll
            for (int nt = 0; nt < 8; nt++) {
                xA[2*nt]   = fmaxf(acc[mt][nt][0] + pb2[nt].x, 0.f);
                xA[2*nt+1] = fmaxf(acc[mt][nt][1] + pb2[nt].y, 0.f);
                xB[2*nt]   = fmaxf(acc[mt][nt][2] + pb2[nt].x, 0.f);
                xB[2*nt+1] = fmaxf(acc[mt][nt][3] + pb2[nt].y, 0.f);
                sA += xA[2*nt] + xA[2*nt+1];
                sB += xB[2*nt] + xB[2*nt+1];
            }
            sA += __shfl_xor_sync(0xffffffffu, sA, 1);
            sA += __shfl_xor_sync(0xffffffffu, sA, 2);
            sB += __shfl_xor_sync(0xffffffffu, sB, 1);
            sB += __shfl_xor_sync(0xffffffffu, sB, 2);
            float muA = sA * (1.f/64.f), muB = sB * (1.f/64.f);
            float vA = 0.f, vB = 0.f;
            #pragma unroll
            for (int t = 0; t < 16; t++) {
                float dA = xA[t] - muA; vA += dA*dA;
                float dB = xB[t] - muB; vB += dB*dB;
            }
            vA += __shfl_xor_sync(0xffffffffu, vA, 1);
            vA += __shfl_xor_sync(0xffffffffu, vA, 2);
            vB += __shfl_xor_sync(0xffffffffu, vB, 1);
            vB += __shfl_xor_sync(0xffffffffu, vB, 2);
            float rsA = 1.f / sqrtf(vA * (1.f/64.f) + 1e-5f);
            float rsB = 1.f / sqrtf(vB * (1.f/64.f) + 1e-5f);
            float dA = 0.f, dB = 0.f;
            #pragma unroll
            for (int nt = 0; nt < 8; nt++) {
                dA = fmaf(fmaf((xA[2*nt]   - muA)*rsA, pg2[nt].x, pbe2[nt].x), pw3[nt].x, dA);
                dA = fmaf(fmaf((xA[2*nt+1] - muA)*rsA, pg2[nt].y, pbe2[nt].y), pw3[nt].y, dA);
                dB = fmaf(fmaf((xB[2*nt]   - muB)*rsB, pg2[nt].x, pbe2[nt].x), pw3[nt].x, dB);
                dB = fmaf(fmaf((xB[2*nt+1] - muB)*rsB, pg2[nt].y, pbe2[nt].y), pw3[nt].y, dB);
            }
            dA += __shfl_xor_sync(0xffffffffu, dA, 1);
            dA += __shfl_xor_sync(0xffffffffu, dA, 2);
            dB += __shfl_xor_sync(0xffffffffu, dB, 1);
            dB += __shfl_xor_sync(0xffffffffu, dB, 2);
            if ((lane & 3) == 0) {
                int eA = e0 + mt*16 + q;
                int cA = c_base + eA;
                if (cA < L) lrow[cA] = dA + b3v;
                int cB = cA + 8;
                if (cB < L) lrow[cB] = dB + b3v;
            }
        }
    }
}

// ---------------- K4: gumbel argmax + scatter 1.0 ----------------
__global__ void k_argmax(const float* __restrict__ gumbel, float* __restrict__ out)
{
    int row = blockIdx.x * 8 + (threadIdx.x >> 5);
    if (row >= NROWS) return;
    int lane = threadIdx.x & 31;
    int i  = row % TT;
    int sb = row / TT;
    int b  = sb & 7;
    int L  = 192 + i;

    const float* lg = g_logits + (size_t)((b*TT + i)) * NSRC;
    const float* gb = gumbel   + (size_t)row * NSRC;

    float best = -__int_as_float(0x7f800000);
    int bidx = 0;
    int c = lane;
    for (; c + 32 < L; c += 64) {
        float v0 = __ldg(&lg[c])      + __ldg(&gb[c]);
        float v1 = __ldg(&lg[c + 32]) + __ldg(&gb[c + 32]);
        if (v0 > best) { best = v0; bidx = c; }
        if (v1 > best) { best = v1; bidx = c + 32; }
    }
    for (; c < L; c += 32) {
        float v = __ldg(&lg[c]) + __ldg(&gb[c]);
        if (v > best) { best = v; bidx = c; }
    }
    #pragma unroll
    for (int o = 16; o; o >>= 1) {
        float ov = __shfl_xor_sync(0xffffffffu, best, o);
        int   oi = __shfl_xor_sync(0xffffffffu, bidx, o);
        if (ov > best || (ov == best && oi < bidx)) { best = ov; bidx = oi; }
    }
    if (lane == 0)
        out[((size_t)(b*NNODE) + 192 + i) * NNODE + bidx] = 1.0f;
}

// ---------------- launch ----------------
extern "C" void kernel_launch(void* const* d_in, const int* in_sizes, int n_in,
                              void* d_out, int out_size)
{
    const float* nodes = (const float*)d_in[0];
    const float* w1    = (const float*)d_in[1];
    const float* b1    = (const float*)d_in[2];
    const float* g1    = (const float*)d_in[3];
    const float* be1   = (const float*)d_in[4];
    const float* w2    = (const float*)d_in[5];
    const float* b2    = (const float*)d_in[6];
    const float* g2    = (const float*)d_in[7];
    const float* be2   = (const float*)d_in[8];
    const float* w3    = (const float*)d_in[9];
    const float* b3    = (const float*)d_in[10];
    const float* gum   = (const float*)d_in[11];
    float* out = (float*)d_out;

    cudaFuncSetAttribute(k_edges, cudaFuncAttributeMaxDynamicSharedMemorySize,
                         SMEM_BYTES);

    // launches 1-5 then k_edges as #6: ncu (-s 5 -c 1) profiles k_edges.
    k_splitw2<<<16, 256>>>(w2);                   // 1
    k_precompute<<<256, 256>>>(nodes, w1, b1);    // 2
    k_dummy<<<1, 32>>>();                         // 3
    k_dummy<<<1, 32>>>();                         // 4
    k_dummy<<<1, 32>>>();                         // 5
    k_edges<<<dim3(3, TT, BB), 128, SMEM_BYTES>>>(b2, g2, be2, w3, b3, g1, be1); // 6
    cudaMemsetAsync(out, 0, (size_t)out_size * sizeof(float));
    k_argmax<<<NROWS / 8, 256>>>(gum, out);
}

// round 9
// speedup vs baseline: 4.1950x; 1.0472x over previous
#include <cuda_runtime.h>
#include <cuda_fp16.h>
#include <cstdint>

// Problem constants (static per reference)
#define BB    8
#define NNODE 384
#define FF    64
#define TT    192
#define NSRC  383         // T + TAU - 1
#define NROWS (5*BB*TT)   // S*B*192 = 7680 argmax rows

// ---------------- device scratch (no allocs allowed) ----------------
__device__ float g_P[BB*NNODE*FF];          // nodes @ w1_top + b1
__device__ float g_Q[BB*NNODE*FF];          // nodes @ w1_bot
__device__ float g_logits[BB*TT*NSRC];      // per-edge logits
__device__ __half g_w2split[2*64*64];       // [plane][j][k] = split_p(w2[k][j])

// ---------------- helpers ----------------
// exact 2-way fp16 split of fp32: v = h + m + r, |r| <= 2^-24 |v|
__device__ __forceinline__ void split2(float v, __half& h, __half& m) {
    h = __float2half_rn(v);
    float r1 = v - __half2float(h);        // exact
    m = __float2half_rn(r1);
}
__device__ __forceinline__ uint32_t pack_h2(__half a, __half b) {
    __half2 t = __halves2half2(a, b);      // a = low half (even k)
    return *reinterpret_cast<uint32_t*>(&t);
}
__device__ __forceinline__ uint32_t smem_u32(const void* p) {
    return (uint32_t)__cvta_generic_to_shared(p);
}
// m16n8k16 row.col f32.f16.f16.f32 (plain sm_80+ PTX; HMMA on sm_103a)
__device__ __forceinline__ void mma16816(float* c, const uint32_t* a,
                                         uint32_t b0, uint32_t b1) {
    asm volatile(
        "mma.sync.aligned.m16n8k16.row.col.f32.f16.f16.f32 "
        "{%0,%1,%2,%3}, {%4,%5,%6,%7}, {%8,%9}, {%0,%1,%2,%3};"
        : "+f"(c[0]), "+f"(c[1]), "+f"(c[2]), "+f"(c[3])
        : "r"(a[0]), "r"(a[1]), "r"(a[2]), "r"(a[3]), "r"(b0), "r"(b1));
}
__device__ __forceinline__ void ldsm_x4(uint32_t* r, uint32_t addr) {
    asm volatile("ldmatrix.sync.aligned.m8n8.x4.shared.b16 {%0,%1,%2,%3}, [%4];"
                 : "=r"(r[0]), "=r"(r[1]), "=r"(r[2]), "=r"(r[3]) : "r"(addr));
}

// ---------------- K1: factor layer 1 per-node (+ fused w2 split) ----------
__global__ void k_precompute(const float* __restrict__ nodes,
                             const float* __restrict__ w1,
                             const float* __restrict__ b1,
                             const float* __restrict__ w2)
{
    __shared__ float w1s[128*64];
    __shared__ float nds[4][64];
    int tid = threadIdx.x;

    // fused: blocks 0..15 also pre-split w2^T into 2 fp16 planes
    if (blockIdx.x < 16) {
        int idx = blockIdx.x * 256 + tid;       // 4096 = [j][k]
        int j = idx >> 6, k = idx & 63;
        float v = w2[k*64 + j];
        __half h, m;
        split2(v, h, m);
        g_w2split[idx]        = h;
        g_w2split[4096 + idx] = m;
    }

    // stage w1 as float4 (8 per thread)
    {
        const float4* src = (const float4*)w1;
        float4* dst = (float4*)w1s;
        #pragma unroll
        for (int t = 0; t < 8; t++) dst[tid + 256*t] = src[tid + 256*t];
    }
    __syncthreads();
    int f = tid & 63, slot = tid >> 6;
    int row0 = blockIdx.x * 12;                 // 256 blocks * 12 rows = 3072
    for (int r = 0; r < 12; r += 4) {
        int row = row0 + r + slot;
        nds[slot][f] = nodes[row*64 + f];
        __syncthreads();
        float accp = b1[f], accq = 0.f;
        #pragma unroll
        for (int k = 0; k < 64; k++) {
            float nv = nds[slot][k];
            accp = fmaf(nv, w1s[k*64 + f],       accp);
            accq = fmaf(nv, w1s[(64+k)*64 + f],  accq);
        }
        g_P[row*64 + f] = accp;
        g_Q[row*64 + f] = accq;
        __syncthreads();
    }
}

// ---------------- K2: fused edge MLP via mma.sync fp16x2 + LDSM ----------
// 128 threads, 128 edges/block. Also zeroes its slice of the output grid
// (before the ragged early-exit) so no separate memset launch is needed.
#define A_BASE   2048
#define B_BASE   (A_BASE + 2*16384)          // 34816
#define SMEM_BYTES (B_BASE + 2*8192)         // 51200
__global__ void __launch_bounds__(128, 3) k_edges(
    const float* __restrict__ b2, const float* __restrict__ g2,
    const float* __restrict__ be2, const float* __restrict__ w3,
    const float* __restrict__ b3, const float* __restrict__ g1,
    const float* __restrict__ be1, float4* __restrict__ out4)
{
    extern __shared__ __align__(128) char smem[];
    float* smf    = (float*)smem;
    float* sp_p   = smf;                     // 7x64 param block (1792B < 2048)
    float* sp_g1  = sp_p  + 64;
    float* sp_be1 = sp_g1 + 64;
    float* sp_b2  = sp_be1+ 64;
    float* sp_g2  = sp_b2 + 64;
    float* sp_be2 = sp_g2 + 64;
    float* sp_w3  = sp_be2+ 64;

    int i = blockIdx.y, b = blockIdx.z;
    int tid  = threadIdx.x;

    // ---- fused output zeroing: 4608 blocks x 64 float4 = full 4.7MB grid ----
    {
        int bid = blockIdx.x + 3*(blockIdx.y + TT*blockIdx.z);   // 0..4607
        if (tid < 64)
            out4[bid*64 + tid] = make_float4(0.f, 0.f, 0.f, 0.f);
    }

    int sink = 192 + i;
    int L = sink;
    int c_base = blockIdx.x * 128;
    if (c_base >= L) return;                 // uniform early exit (before syncs)

    int lane = tid & 31;
    int w    = tid >> 5;

    // stage B planes (pre-split fp16 w2^T), swizzled: 1024 uint4
    {
        const uint4* src = (const uint4*)g_w2split;
        for (int idx = tid; idx < 1024; idx += 128) {
            int p = idx >> 9, q = idx & 511;
            int j = q >> 3, u = q & 7;
            *(uint4*)(smem + B_BASE + p*8192 + j*128 + ((u ^ (j & 7)) << 4)) = src[idx];
        }
    }
    if (tid < 64) {
        sp_p[tid]  = g_P[(b*NNODE + sink)*64 + tid];
        sp_g1[tid] = g1[tid];
        sp_be1[tid]= be1[tid];
        sp_b2[tid] = b2[tid];
        sp_g2[tid] = g2[tid];
        sp_be2[tid]= be2[tid];
        sp_w3[tid] = w3[tid];
    }
    __syncthreads();

    // ---- phase 1: thread-per-edge LN1 + fp16 split -> A planes ----
    {
        int e = tid;
        int c = c_base + e;                  // < 384: safe read
        const float4* qrow = (const float4*)&g_Q[((b*NNODE) + c)*64];
        float4 x[16];
        float s = 0.f;
        #pragma unroll
        for (int u = 0; u < 16; u++) {
            float4 q = __ldg(&qrow[u]);
            float4 p = *(const float4*)&sp_p[u*4];
            x[u].x = fmaxf(p.x + q.x, 0.f);
            x[u].y = fmaxf(p.y + q.y, 0.f);
            x[u].z = fmaxf(p.z + q.z, 0.f);
            x[u].w = fmaxf(p.w + q.w, 0.f);
            s += x[u].x + x[u].y + x[u].z + x[u].w;
        }
        float mu = s * (1.f/64.f);
        float vs = 0.f;
        #pragma unroll
        for (int u = 0; u < 16; u++) {
            float d0 = x[u].x - mu, d1 = x[u].y - mu;
            float d2 = x[u].z - mu, d3 = x[u].w - mu;
            vs += d0*d0 + d1*d1 + d2*d2 + d3*d3;
        }
        float rstd = 1.f / sqrtf(vs * (1.f/64.f) + 1e-5f);
        #pragma unroll
        for (int u = 0; u < 16; u++) {
            float4 gv = *(const float4*)&sp_g1[u*4];
            float4 bv = *(const float4*)&sp_be1[u*4];
            x[u].x = fmaf((x[u].x - mu)*rstd, gv.x, bv.x);
            x[u].y = fmaf((x[u].y - mu)*rstd, gv.y, bv.y);
            x[u].z = fmaf((x[u].z - mu)*rstd, gv.z, bv.z);
            x[u].w = fmaf((x[u].w - mu)*rstd, gv.w, bv.w);
        }
        int rowoff = e * 128;
        #pragma unroll
        for (int u2 = 0; u2 < 8; u2++) {
            float4 a0 = x[2*u2], a1 = x[2*u2 + 1];
            float vv[8] = {a0.x, a0.y, a0.z, a0.w, a1.x, a1.y, a1.z, a1.w};
            __half h[8], m[8];
            #pragma unroll
            for (int t = 0; t < 8; t++) split2(vv[t], h[t], m[t]);
            uint4 uh = make_uint4(pack_h2(h[0],h[1]), pack_h2(h[2],h[3]),
                                  pack_h2(h[4],h[5]), pack_h2(h[6],h[7]));
            uint4 um = make_uint4(pack_h2(m[0],m[1]), pack_h2(m[2],m[3]),
                                  pack_h2(m[4],m[5]), pack_h2(m[6],m[7]));
            int phys = rowoff + ((u2 ^ (e & 7)) << 4);
            *(uint4*)(smem + A_BASE         + phys) = uh;
            *(uint4*)(smem + A_BASE + 16384 + phys) = um;
        }
    }
    __syncthreads();

    // ---- phase 2: HMMA GEMM, 3 products, LDSM fragment loads ----
    int e0 = w * 32;
    int q  = lane >> 2;          // fragment row group
    int kq = (lane & 3) * 2;     // fragment col pair

    float acc[2][8][4];
    #pragma unroll
    for (int mt = 0; mt < 2; mt++)
        #pragma unroll
        for (int nt = 0; nt < 8; nt++)
            #pragma unroll
            for (int t = 0; t < 4; t++) acc[mt][nt][t] = 0.f;

    uint32_t Ah32 = smem_u32(smem + A_BASE);
    uint32_t Am32 = Ah32 + 16384;
    uint32_t Bh32 = smem_u32(smem + B_BASE);
    uint32_t Bm32 = Bh32 + 8192;

    // per-lane ldmatrix row addressing
    int sub = lane >> 3, l8 = lane & 7;
    // A (per mt): sub0:(rows+0..7, k0) sub1:(rows+8..15, k0) sub2:(+0..7, k8) sub3:(+8..15, k8)
    int rA[2], rA7[2];
    #pragma unroll
    for (int mt = 0; mt < 2; mt++) {
        int r = e0 + mt*16 + ((sub & 1) << 3) + l8;
        rA[mt] = r * 128;
        rA7[mt] = r & 7;
    }
    int kbitA = sub >> 1;
    // B (per nt-pair p -> nt=2p,2p+1): sub0:(j 2p, k0) sub1:(2p, k8) sub2:(2p+1, k0) sub3:(2p+1, k8)
    int rB[4], rB7[4];
    #pragma unroll
    for (int p = 0; p < 4; p++) {
        int j = p*16 + ((sub >> 1) << 3) + l8;
        rB[p] = j * 128;
        rB7[p] = j & 7;
    }
    int kbitB = sub & 1;

    #pragma unroll
    for (int ks = 0; ks < 4; ks++) {
        uint32_t ah[2][4], am[2][4];
        #pragma unroll
        for (int mt = 0; mt < 2; mt++) {
            uint32_t off = rA[mt] + (((2*ks + kbitA) ^ rA7[mt]) << 4);
            ldsm_x4(ah[mt], Ah32 + off);
            ldsm_x4(am[mt], Am32 + off);
        }
        uint32_t bh[8][2], bm[8][2];
        #pragma unroll
        for (int p = 0; p < 4; p++) {
            uint32_t off = rB[p] + (((2*ks + kbitB) ^ rB7[p]) << 4);
            uint32_t t4[4];
            ldsm_x4(t4, Bh32 + off);
            bh[2*p][0] = t4[0]; bh[2*p][1] = t4[1];
            bh[2*p+1][0] = t4[2]; bh[2*p+1][1] = t4[3];
            ldsm_x4(t4, Bm32 + off);
            bm[2*p][0] = t4[0]; bm[2*p][1] = t4[1];
            bm[2*p+1][0] = t4[2]; bm[2*p+1][1] = t4[3];
        }
        #pragma unroll
        for (int nt = 0; nt < 8; nt++) {
            mma16816(acc[0][nt], ah[0], bh[nt][0], bh[nt][1]);   // h*h
            mma16816(acc[1][nt], ah[1], bh[nt][0], bh[nt][1]);
            mma16816(acc[0][nt], ah[0], bm[nt][0], bm[nt][1]);   // h*m
            mma16816(acc[1][nt], ah[1], bm[nt][0], bm[nt][1]);
            mma16816(acc[0][nt], am[0], bh[nt][0], bh[nt][1]);   // m*h
            mma16816(acc[1][nt], am[1], bh[nt][0], bh[nt][1]);
        }
    }

    // ---- epilogue: relu + LN2 via quad reductions -> logits ----
    {
        float2 pb2[8], pg2[8], pbe2[8], pw3[8];
        #pragma unroll
        for (int nt = 0; nt < 8; nt++) {
            int jc = nt*8 + kq;
            pb2[nt]  = *(const float2*)&sp_b2[jc];
            pg2[nt]  = *(const float2*)&sp_g2[jc];
            pbe2[nt] = *(const float2*)&sp_be2[jc];
            pw3[nt]  = *(const float2*)&sp_w3[jc];
        }
        float b3v = __ldg(&b3[0]);
        float* lrow = g_logits + (b*TT + i)*NSRC;

        #pragma unroll
        for (int mt = 0; mt < 2; mt++) {
            // rows rA = e0 + mt*16 + q, rB = rA + 8; thread holds 16 cols each
            float xA[16], xB[16];
            float sA = 0.f, sB = 0.f;
            #pragma unroll
            for (int nt = 0; nt < 8; nt++) {
                xA[2*nt]   = fmaxf(acc[mt][nt][0] + pb2[nt].x, 0.f);
                xA[2*nt+1] = fmaxf(acc[mt][nt][1] + pb2[nt].y, 0.f);
                xB[2*nt]   = fmaxf(acc[mt][nt][2] + pb2[nt].x, 0.f);
                xB[2*nt+1] = fmaxf(acc[mt][nt][3] + pb2[nt].y, 0.f);
                sA += xA[2*nt] + xA[2*nt+1];
                sB += xB[2*nt] + xB[2*nt+1];
            }
            sA += __shfl_xor_sync(0xffffffffu, sA, 1);
            sA += __shfl_xor_sync(0xffffffffu, sA, 2);
            sB += __shfl_xor_sync(0xffffffffu, sB, 1);
            sB += __shfl_xor_sync(0xffffffffu, sB, 2);
            float muA = sA * (1.f/64.f), muB = sB * (1.f/64.f);
            float vA = 0.f, vB = 0.f;
            #pragma unroll
            for (int t = 0; t < 16; t++) {
                float dA = xA[t] - muA; vA += dA*dA;
                float dB = xB[t] - muB; vB += dB*dB;
            }
            vA += __shfl_xor_sync(0xffffffffu, vA, 1);
            vA += __shfl_xor_sync(0xffffffffu, vA, 2);
            vB += __shfl_xor_sync(0xffffffffu, vB, 1);
            vB += __shfl_xor_sync(0xffffffffu, vB, 2);
            float rsA = 1.f / sqrtf(vA * (1.f/64.f) + 1e-5f);
            float rsB = 1.f / sqrtf(vB * (1.f/64.f) + 1e-5f);
            float dA = 0.f, dB = 0.f;
            #pragma unroll
            for (int nt = 0; nt < 8; nt++) {
                dA = fmaf(fmaf((xA[2*nt]   - muA)*rsA, pg2[nt].x, pbe2[nt].x), pw3[nt].x, dA);
                dA = fmaf(fmaf((xA[2*nt+1] - muA)*rsA, pg2[nt].y, pbe2[nt].y), pw3[nt].y, dA);
                dB = fmaf(fmaf((xB[2*nt]   - muB)*rsB, pg2[nt].x, pbe2[nt].x), pw3[nt].x, dB);
                dB = fmaf(fmaf((xB[2*nt+1] - muB)*rsB, pg2[nt].y, pbe2[nt].y), pw3[nt].y, dB);
            }
            dA += __shfl_xor_sync(0xffffffffu, dA, 1);
            dA += __shfl_xor_sync(0xffffffffu, dA, 2);
            dB += __shfl_xor_sync(0xffffffffu, dB, 1);
            dB += __shfl_xor_sync(0xffffffffu, dB, 2);
            if ((lane & 3) == 0) {
                int eA = e0 + mt*16 + q;
                int cA = c_base + eA;
                if (cA < L) lrow[cA] = dA + b3v;
                int cB = cA + 8;
                if (cB < L) lrow[cB] = dB + b3v;
            }
        }
    }
}

// ---------------- K4: gumbel argmax + scatter 1.0 ----------------
__global__ void k_argmax(const float* __restrict__ gumbel, float* __restrict__ out)
{
    int row = blockIdx.x * 8 + (threadIdx.x >> 5);
    if (row >= NROWS) return;
    int lane = threadIdx.x & 31;
    int i  = row % TT;
    int sb = row / TT;
    int b  = sb & 7;
    int L  = 192 + i;

    const float* lg = g_logits + (size_t)((b*TT + i)) * NSRC;
    const float* gb = gumbel   + (size_t)row * NSRC;

    float best = -__int_as_float(0x7f800000);
    int bidx = 0;
    int c = lane;
    for (; c + 96 < L; c += 128) {           // 4-way unroll for MLP
        float v0 = __ldg(&lg[c])      + __ldg(&gb[c]);
        float v1 = __ldg(&lg[c + 32]) + __ldg(&gb[c + 32]);
        float v2 = __ldg(&lg[c + 64]) + __ldg(&gb[c + 64]);
        float v3 = __ldg(&lg[c + 96]) + __ldg(&gb[c + 96]);
        if (v0 > best) { best = v0; bidx = c; }
        if (v1 > best) { best = v1; bidx = c + 32; }
        if (v2 > best) { best = v2; bidx = c + 64; }
        if (v3 > best) { best = v3; bidx = c + 96; }
    }
    for (; c < L; c += 32) {
        float v = __ldg(&lg[c]) + __ldg(&gb[c]);
        if (v > best) { best = v; bidx = c; }
    }
    #pragma unroll
    for (int o = 16; o; o >>= 1) {
        float ov = __shfl_xor_sync(0xffffffffu, best, o);
        int   oi = __shfl_xor_sync(0xffffffffu, bidx, o);
        if (ov > best || (ov == best && oi < bidx)) { best = ov; bidx = oi; }
    }
    if (lane == 0)
        out[((size_t)(b*NNODE) + 192 + i) * NNODE + bidx] = 1.0f;
}

// ---------------- launch ----------------
extern "C" void kernel_launch(void* const* d_in, const int* in_sizes, int n_in,
                              void* d_out, int out_size)
{
    const float* nodes = (const float*)d_in[0];
    const float* w1    = (const float*)d_in[1];
    const float* b1    = (const float*)d_in[2];
    const float* g1    = (const float*)d_in[3];
    const float* be1   = (const float*)d_in[4];
    const float* w2    = (const float*)d_in[5];
    const float* b2    = (const float*)d_in[6];
    const float* g2    = (const float*)d_in[7];
    const float* be2   = (const float*)d_in[8];
    const float* w3    = (const float*)d_in[9];
    const float* b3    = (const float*)d_in[10];
    const float* gum   = (const float*)d_in[11];
    float* out = (float*)d_out;

    cudaFuncSetAttribute(k_edges, cudaFuncAttributeMaxDynamicSharedMemorySize,
                         SMEM_BYTES);

    k_precompute<<<256, 256>>>(nodes, w1, b1, w2);
    k_edges<<<dim3(3, TT, BB), 128, SMEM_BYTES>>>(b2, g2, be2, w3, b3, g1, be1,
                                                  (float4*)out);
    k_argmax<<<NROWS / 8, 256>>>(gum, out);
}